// round 7
// baseline (speedup 1.0000x reference)
#include <cuda_runtime.h>

#define N_SAMP 384
#define M 12
#define NP 6
#define UC (M * NP)      // 72 complex entries per sample

typedef unsigned long long u64;

// Duplicated packed operand formats (built once in stage 1):
// g_u1d entry e=(k*6+b): [2e]=(re,im)=bp  [2e+1]=(-im,re)=bn
// g_u2d entry e=(k*6+a): [2e]=(cre,cre)=aR [2e+1]=(cim,cim)=aI  (c = conj(U2))
// cmul(c,u1) = aR.*bp + aI.*bn  -> two packed FFMA2.
__device__ __align__(16) float2 g_u1d[N_SAMP * UC * 2];
__device__ __align__(16) float2 g_u2d[N_SAMP * UC * 2];

__device__ __forceinline__ float2 cmul(float2 a, float2 b) {
    return make_float2(a.x * b.x - a.y * b.y, a.x * b.y + a.y * b.x);
}

// ---- packed f32x2 helpers ----
__device__ __forceinline__ u64 pk2(float lo, float hi) {
    u64 d; asm("mov.b64 %0, {%1,%2};" : "=l"(d) : "f"(lo), "f"(hi)); return d;
}
__device__ __forceinline__ float2 upk(u64 d) {
    float2 r; asm("mov.b64 {%0,%1}, %2;" : "=f"(r.x), "=f"(r.y) : "l"(d)); return r;
}
__device__ __forceinline__ u64 ffma2(u64 a, u64 b, u64 c) {
    u64 d; asm("fma.rn.f32x2 %0, %1, %2, %3;" : "=l"(d) : "l"(a), "l"(b), "l"(c)); return d;
}
__device__ __forceinline__ u64 fmul2(u64 a, u64 b) {
    u64 d; asm("mul.rn.f32x2 %0, %1, %2;" : "=l"(d) : "l"(a), "l"(b)); return d;
}
__device__ __forceinline__ u64 fadd2(u64 a, u64 b) {
    u64 d; asm("add.rn.f32x2 %0, %1, %2;" : "=l"(d) : "l"(a), "l"(b)); return d;
}

// ---------------------------------------------------------------------------
// Stage 1 (single launch, grid=768): U(x) = A @ diag(exp(ix)) @ B, first NP cols,
// written out in duplicated packed formats.
// ---------------------------------------------------------------------------
__global__ void build_u_kernel(const float* __restrict__ x1,
                               const float* __restrict__ x2,
                               const float* __restrict__ A_re,
                               const float* __restrict__ A_im,
                               const float* __restrict__ B_re,
                               const float* __restrict__ B_im)
{
    __shared__ float2 ph[M];
    __shared__ float2 sA[M * M];
    __shared__ float2 sB[M][NP];

    const int s      = blockIdx.x;
    const int tid    = threadIdx.x;
    const int second = (s >= N_SAMP);
    const int ss     = second ? s - N_SAMP : s;
    const float* x   = second ? x2 : x1;

    if (tid < M * M) sA[tid] = make_float2(A_re[tid], A_im[tid]);
    if (tid < M * NP) {
        int b = tid / NP, c = tid - b * NP;
        sB[b][c] = make_float2(B_re[b * M + c], B_im[b * M + c]);
    }
    if (tid < M) {
        float sn, cs;
        sincosf(x[ss * M + tid], &sn, &cs);
        ph[tid] = make_float2(cs, sn);
    }
    __syncthreads();

    if (tid < M * NP) {
        const int a = tid / NP;
        const int c = tid - a * NP;
        float2 acc = make_float2(0.f, 0.f);
#pragma unroll
        for (int b = 0; b < M; ++b) {
            float2 t  = cmul(ph[b], sB[b][c]);
            float2 Av = sA[a * M + b];
            acc.x += Av.x * t.x - Av.y * t.y;
            acc.y += Av.x * t.y + Av.y * t.x;
        }
        const int base = (ss * UC + tid) * 2;
        if (second) {
            g_u2d[base + 0] = make_float2(acc.x, acc.x);     // aR (conj re)
            g_u2d[base + 1] = make_float2(-acc.y, -acc.y);   // aI (conj im)
        } else {
            g_u1d[base + 0] = make_float2(acc.x, acc.y);     // bp
            g_u1d[base + 1] = make_float2(-acc.y, acc.x);    // bn
        }
    }
}

// ---------------------------------------------------------------------------
// Stage 2: W[a][b] = sum_k conjU2[j][k][a]*U1[i][k][b] (FFMA2, 128-bit LDS),
// then Glynn permanent (Gray chain, packed rowsums). 16x16 pairs / 256 thr.
// ---------------------------------------------------------------------------
#define SP 146   // smem pitch in u64 = 73 x 16B (odd 16B stride -> conflict-free)

__device__ __forceinline__ float2 prod6(const u64* r) {
    float2 a0 = upk(r[0]), a1 = upk(r[1]), a2 = upk(r[2]);
    float2 a3 = upk(r[3]), a4 = upk(r[4]), a5 = upk(r[5]);
    float2 p01 = cmul(a0, a1);
    float2 p23 = cmul(a2, a3);
    float2 p45 = cmul(a4, a5);
    return cmul(cmul(p01, p23), p45);
}

__global__ __launch_bounds__(256) void pair_kernel(float* __restrict__ out)
{
    __shared__ __align__(16) u64 s1[16 * SP];
    __shared__ __align__(16) u64 s2[16 * SP];

    const int i0  = blockIdx.y * 16;
    const int j0  = blockIdx.x * 16;
    const int tid = threadIdx.x;

    // 128-bit staged copy: 16 rows x 72 ulonglong2 per array.
    const ulonglong2* __restrict__ gu1 = (const ulonglong2*)g_u1d;
    const ulonglong2* __restrict__ gu2 = (const ulonglong2*)g_u2d;
    for (int e = tid; e < 16 * UC; e += 256) {
        int l = e / UC;
        int r = e - l * UC;
        ((ulonglong2*)(s1 + l * SP))[r] = gu1[(i0 + l) * UC + r];
        ((ulonglong2*)(s2 + l * SP))[r] = gu2[(j0 + l) * UC + r];
    }
    __syncthreads();

    const int lj = tid & 15;        // j fastest -> coalesced output
    const int li = tid >> 4;
    const ulonglong2* __restrict__ p1 = (const ulonglong2*)(s1 + li * SP); // {bp,bn}
    const ulonglong2* __restrict__ p2 = (const ulonglong2*)(s2 + lj * SP); // {aR,aI}

    u64 W[NP][NP];

    // k = 0 initializes W (no zero-init, no add-to-zero)
    {
        ulonglong2 bb[NP], aa[NP];
#pragma unroll
        for (int e = 0; e < NP; ++e) { bb[e] = p1[e]; aa[e] = p2[e]; }
#pragma unroll
        for (int a = 0; a < NP; ++a)
#pragma unroll
            for (int b = 0; b < NP; ++b)
                W[a][b] = ffma2(aa[a].y, bb[b].y, fmul2(aa[a].x, bb[b].x));
    }

#pragma unroll
    for (int k = 1; k < M; ++k) {
        ulonglong2 bb[NP], aa[NP];
#pragma unroll
        for (int e = 0; e < NP; ++e) { bb[e] = p1[k * NP + e]; aa[e] = p2[k * NP + e]; }
#pragma unroll
        for (int a = 0; a < NP; ++a)
#pragma unroll
            for (int b = 0; b < NP; ++b) {
                W[a][b] = ffma2(aa[a].x, bb[b].x, W[a][b]);
                W[a][b] = ffma2(aa[a].y, bb[b].y, W[a][b]);
            }
    }

    // --- Glynn permanent, n=6, single Gray chain, packed rowsums ---
    const u64 PL2 = pk2(2.f, 2.f);
    const u64 MI2 = pk2(-2.f, -2.f);

    u64 r[NP];
#pragma unroll
    for (int j = 0; j < NP; ++j) {
        u64 t01 = fadd2(W[0][j], W[1][j]);
        u64 t23 = fadd2(W[2][j], W[3][j]);
        u64 t45 = fadd2(W[4][j], W[5][j]);
        r[j] = fadd2(fadd2(t01, t23), t45);
    }

    float2 acc = prod6(r);

#pragma unroll
    for (int t = 1; t < 32; ++t) {
        const int bit = (t & 1) ? 0 : ((t & 2) ? 1 : ((t & 4) ? 2 : ((t & 8) ? 3 : 4)));
        const int a   = bit + 1;                              // flipped row (1..5)
        const bool neg = (((t ^ (t >> 1)) >> bit) & 1) != 0;
        const u64 c2  = neg ? MI2 : PL2;
        const float sg = (t & 1) ? -1.f : 1.f;                // parity (-1)^t

#pragma unroll
        for (int j = 0; j < NP; ++j)
            r[j] = ffma2(c2, W[a][j], r[j]);

        float2 p = prod6(r);
        acc.x += sg * p.x;
        acc.y += sg * p.y;
    }

    // perm = acc / 32 ; K = |perm|^2 = |acc|^2 / 1024
    const float K = (acc.x * acc.x + acc.y * acc.y) * (1.0f / 1024.0f);
    out[(i0 + li) * N_SAMP + (j0 + lj)] = K;
}

// ---------------------------------------------------------------------------
extern "C" void kernel_launch(void* const* d_in, const int* in_sizes, int n_in,
                              void* d_out, int out_size)
{
    const float* x1   = (const float*)d_in[0];
    const float* x2   = (const float*)d_in[1];
    const float* A_re = (const float*)d_in[2];
    const float* A_im = (const float*)d_in[3];
    const float* B_re = (const float*)d_in[4];
    const float* B_im = (const float*)d_in[5];

    build_u_kernel<<<2 * N_SAMP, 160>>>(x1, x2, A_re, A_im, B_re, B_im);

    dim3 grid(N_SAMP / 16, N_SAMP / 16);   // 24 x 24
    pair_kernel<<<grid, 256>>>((float*)d_out);
}

// round 8
// speedup vs baseline: 1.0088x; 1.0088x over previous
#include <cuda_runtime.h>

#define N_SAMP 384
#define M 12
#define NP 6
#define UC (M * NP)      // 72 complex entries per sample

typedef unsigned long long u64;

// Duplicated packed operand formats (built once in stage 1):
// g_u1d entry e=(k*6+b): [2e]=(re,im)=bp  [2e+1]=(-im,re)=bn
// g_u2d entry e=(k*6+a): [2e]=(cre,cre)=aR [2e+1]=(cim,cim)=aI  (c = conj(U2))
// cmul(c,u1) = aR.*bp + aI.*bn  -> two packed FFMA2.
__device__ float2 g_u1d[N_SAMP * UC * 2];
__device__ float2 g_u2d[N_SAMP * UC * 2];

__device__ __forceinline__ float2 cmul(float2 a, float2 b) {
    return make_float2(a.x * b.x - a.y * b.y, a.x * b.y + a.y * b.x);
}

// ---- packed f32x2 helpers ----
__device__ __forceinline__ u64 pk2(float lo, float hi) {
    u64 d; asm("mov.b64 %0, {%1,%2};" : "=l"(d) : "f"(lo), "f"(hi)); return d;
}
__device__ __forceinline__ float2 upk(u64 d) {
    float2 r; asm("mov.b64 {%0,%1}, %2;" : "=f"(r.x), "=f"(r.y) : "l"(d)); return r;
}
__device__ __forceinline__ u64 ffma2(u64 a, u64 b, u64 c) {
    u64 d; asm("fma.rn.f32x2 %0, %1, %2, %3;" : "=l"(d) : "l"(a), "l"(b), "l"(c)); return d;
}
__device__ __forceinline__ u64 fmul2(u64 a, u64 b) {
    u64 d; asm("mul.rn.f32x2 %0, %1, %2;" : "=l"(d) : "l"(a), "l"(b)); return d;
}
__device__ __forceinline__ u64 fadd2(u64 a, u64 b) {
    u64 d; asm("add.rn.f32x2 %0, %1, %2;" : "=l"(d) : "l"(a), "l"(b)); return d;
}

// ---------------------------------------------------------------------------
// Stage 1 (single launch, grid=768): U(x) = A @ diag(exp(ix)) @ B, first NP cols,
// written out in duplicated packed formats.
// ---------------------------------------------------------------------------
__global__ void build_u_kernel(const float* __restrict__ x1,
                               const float* __restrict__ x2,
                               const float* __restrict__ A_re,
                               const float* __restrict__ A_im,
                               const float* __restrict__ B_re,
                               const float* __restrict__ B_im)
{
    __shared__ float2 ph[M];
    __shared__ float2 sA[M * M];
    __shared__ float2 sB[M][NP];

    const int s      = blockIdx.x;
    const int tid    = threadIdx.x;
    const int second = (s >= N_SAMP);
    const int ss     = second ? s - N_SAMP : s;
    const float* x   = second ? x2 : x1;

    if (tid < M * M) sA[tid] = make_float2(A_re[tid], A_im[tid]);
    if (tid < M * NP) {
        int b = tid / NP, c = tid - b * NP;
        sB[b][c] = make_float2(B_re[b * M + c], B_im[b * M + c]);
    }
    if (tid < M) {
        float sn, cs;
        sincosf(x[ss * M + tid], &sn, &cs);
        ph[tid] = make_float2(cs, sn);
    }
    __syncthreads();

    if (tid < M * NP) {
        const int a = tid / NP;
        const int c = tid - a * NP;
        float2 acc = make_float2(0.f, 0.f);
#pragma unroll
        for (int b = 0; b < M; ++b) {
            float2 t  = cmul(ph[b], sB[b][c]);
            float2 Av = sA[a * M + b];
            acc.x += Av.x * t.x - Av.y * t.y;
            acc.y += Av.x * t.y + Av.y * t.x;
        }
        const int base = (ss * UC + tid) * 2;
        if (second) {
            g_u2d[base + 0] = make_float2(acc.x, acc.x);     // aR (conj re)
            g_u2d[base + 1] = make_float2(-acc.y, -acc.y);   // aI (conj im)
        } else {
            g_u1d[base + 0] = make_float2(acc.x, acc.y);     // bp
            g_u1d[base + 1] = make_float2(-acc.y, acc.x);    // bn
        }
    }
}

// ---------------------------------------------------------------------------
// Stage 2: 2 threads per pair. Thread h owns W columns {3h..3h+2}.
// W[a][c] = sum_k conjU2[j][k][a]*U1[i][k][3h+c]  (FFMA2).
// Glynn: per Gray step each thread updates its 3 packed rowsums, builds the
// partial product of its 3 columns, swaps partials via shfl_xor(1), combines.
// Block 256 thr = 128 pairs = 8(i) x 16(j) tile.
// ---------------------------------------------------------------------------
#define SP 145   // smem pitch in u64 (odd -> row stride hits distinct banks)
#define TI 8
#define TJ 16

__global__ __launch_bounds__(256, 3) void pair_kernel(float* __restrict__ out)
{
    __shared__ u64 s1[TI * SP];
    __shared__ u64 s2[TJ * SP];

    const int i0  = blockIdx.y * TI;
    const int j0  = blockIdx.x * TJ;
    const int tid = threadIdx.x;

    const u64* __restrict__ gu1 = (const u64*)g_u1d;
    const u64* __restrict__ gu2 = (const u64*)g_u2d;
    for (int e = tid; e < TI * (UC * 2); e += 256) {
        int l = e / (UC * 2);
        int r = e - l * (UC * 2);
        s1[l * SP + r] = gu1[(i0 + l) * (UC * 2) + r];
    }
    for (int e = tid; e < TJ * (UC * 2); e += 256) {
        int l = e / (UC * 2);
        int r = e - l * (UC * 2);
        s2[l * SP + r] = gu2[(j0 + l) * (UC * 2) + r];
    }
    __syncthreads();

    const int h  = tid & 1;          // column half: b in {3h, 3h+1, 3h+2}
    const int p  = tid >> 1;         // pair index 0..127
    const int lj = p & 15;
    const int li = p >> 4;           // 0..7
    const u64* __restrict__ p1 = &s1[li * SP + 6 * h];   // this half's bp/bn
    const u64* __restrict__ p2 = &s2[lj * SP];           // full aR/aI row

    u64 W[NP][3];                    // rows a=0..5, own 3 columns

    // k = 0 initializes W
    {
        u64 bb[6];
#pragma unroll
        for (int e = 0; e < 6; ++e) bb[e] = p1[e];
#pragma unroll
        for (int a = 0; a < NP; ++a) {
            const u64 aR = p2[2 * a + 0];
            const u64 aI = p2[2 * a + 1];
#pragma unroll
            for (int c = 0; c < 3; ++c)
                W[a][c] = ffma2(aI, bb[2 * c + 1], fmul2(aR, bb[2 * c]));
        }
    }

#pragma unroll
    for (int k = 1; k < M; ++k) {
        u64 bb[6];
#pragma unroll
        for (int e = 0; e < 6; ++e) bb[e] = p1[k * 12 + e];
#pragma unroll
        for (int a = 0; a < NP; ++a) {
            const u64 aR = p2[k * 12 + 2 * a + 0];
            const u64 aI = p2[k * 12 + 2 * a + 1];
#pragma unroll
            for (int c = 0; c < 3; ++c) {
                W[a][c] = ffma2(aR, bb[2 * c + 0], W[a][c]);
                W[a][c] = ffma2(aI, bb[2 * c + 1], W[a][c]);
            }
        }
    }

    // --- Glynn permanent, n=6, Gray chain; columns split across thread pair ---
    const u64 PL2 = pk2(2.f, 2.f);
    const u64 MI2 = pk2(-2.f, -2.f);

    u64 r[3];
#pragma unroll
    for (int c = 0; c < 3; ++c) {
        u64 t01 = fadd2(W[0][c], W[1][c]);
        u64 t23 = fadd2(W[2][c], W[3][c]);
        u64 t45 = fadd2(W[4][c], W[5][c]);
        r[c] = fadd2(fadd2(t01, t23), t45);
    }

    float2 acc;
    {
        float2 P = cmul(cmul(upk(r[0]), upk(r[1])), upk(r[2]));
        float2 Q;
        Q.x = __shfl_xor_sync(0xffffffffu, P.x, 1);
        Q.y = __shfl_xor_sync(0xffffffffu, P.y, 1);
        acc = cmul(P, Q);
    }

#pragma unroll
    for (int t = 1; t < 32; ++t) {
        const int bit = (t & 1) ? 0 : ((t & 2) ? 1 : ((t & 4) ? 2 : ((t & 8) ? 3 : 4)));
        const int a   = bit + 1;                              // flipped row (1..5)
        const bool neg = (((t ^ (t >> 1)) >> bit) & 1) != 0;
        const u64 c2  = neg ? MI2 : PL2;
        const float sg = (t & 1) ? -1.f : 1.f;                // parity (-1)^t

#pragma unroll
        for (int c = 0; c < 3; ++c)
            r[c] = ffma2(c2, W[a][c], r[c]);

        float2 P = cmul(cmul(upk(r[0]), upk(r[1])), upk(r[2]));
        float2 Q;
        Q.x = __shfl_xor_sync(0xffffffffu, P.x, 1);
        Q.y = __shfl_xor_sync(0xffffffffu, P.y, 1);
        float2 f = cmul(P, Q);
        acc.x += sg * f.x;
        acc.y += sg * f.y;
    }

    // perm = acc / 32 ; K = |perm|^2 = |acc|^2 / 1024
    if (h == 0) {
        const float K = (acc.x * acc.x + acc.y * acc.y) * (1.0f / 1024.0f);
        out[(i0 + li) * N_SAMP + (j0 + lj)] = K;
    }
}

// ---------------------------------------------------------------------------
extern "C" void kernel_launch(void* const* d_in, const int* in_sizes, int n_in,
                              void* d_out, int out_size)
{
    const float* x1   = (const float*)d_in[0];
    const float* x2   = (const float*)d_in[1];
    const float* A_re = (const float*)d_in[2];
    const float* A_im = (const float*)d_in[3];
    const float* B_re = (const float*)d_in[4];
    const float* B_im = (const float*)d_in[5];

    build_u_kernel<<<2 * N_SAMP, 160>>>(x1, x2, A_re, A_im, B_re, B_im);

    dim3 grid(N_SAMP / TJ, N_SAMP / TI);   // 24 x 48
    pair_kernel<<<grid, 256>>>((float*)d_out);
}

// round 9
// speedup vs baseline: 1.1735x; 1.1633x over previous
#include <cuda_runtime.h>

#define N_SAMP 384
#define M 12
#define NP 6
#define UC (M * NP)      // 72 complex entries per sample

typedef unsigned long long u64;

// Duplicated packed operand formats (built once in stage 1):
// g_u1d entry e=(k*6+b): [2e]=(re,im)=bp  [2e+1]=(-im,re)=bn
// g_u2d entry e=(k*6+a): [2e]=(cre,cre)=aR [2e+1]=(cim,cim)=aI  (c = conj(U2))
// cmul(c,u1) = aR.*bp + aI.*bn  -> two packed FFMA2.
__device__ float2 g_u1d[N_SAMP * UC * 2];
__device__ float2 g_u2d[N_SAMP * UC * 2];

__device__ __forceinline__ float2 cmul(float2 a, float2 b) {
    return make_float2(a.x * b.x - a.y * b.y, a.x * b.y + a.y * b.x);
}

// ---- packed f32x2 helpers ----
__device__ __forceinline__ u64 pk2(float lo, float hi) {
    u64 d; asm("mov.b64 %0, {%1,%2};" : "=l"(d) : "f"(lo), "f"(hi)); return d;
}
__device__ __forceinline__ float2 upk(u64 d) {
    float2 r; asm("mov.b64 {%0,%1}, %2;" : "=f"(r.x), "=f"(r.y) : "l"(d)); return r;
}
__device__ __forceinline__ u64 ffma2(u64 a, u64 b, u64 c) {
    u64 d; asm("fma.rn.f32x2 %0, %1, %2, %3;" : "=l"(d) : "l"(a), "l"(b), "l"(c)); return d;
}
__device__ __forceinline__ u64 fmul2(u64 a, u64 b) {
    u64 d; asm("mul.rn.f32x2 %0, %1, %2;" : "=l"(d) : "l"(a), "l"(b)); return d;
}
__device__ __forceinline__ u64 fadd2(u64 a, u64 b) {
    u64 d; asm("add.rn.f32x2 %0, %1, %2;" : "=l"(d) : "l"(a), "l"(b)); return d;
}

// ---------------------------------------------------------------------------
// Stage 1 (single launch, grid=768): U(x) = A @ diag(exp(ix)) @ B, first NP cols,
// written out in duplicated packed formats.
// ---------------------------------------------------------------------------
__global__ void build_u_kernel(const float* __restrict__ x1,
                               const float* __restrict__ x2,
                               const float* __restrict__ A_re,
                               const float* __restrict__ A_im,
                               const float* __restrict__ B_re,
                               const float* __restrict__ B_im)
{
    __shared__ float2 ph[M];
    __shared__ float2 sA[M * M];
    __shared__ float2 sB[M][NP];

    const int s      = blockIdx.x;
    const int tid    = threadIdx.x;
    const int second = (s >= N_SAMP);
    const int ss     = second ? s - N_SAMP : s;
    const float* x   = second ? x2 : x1;

    if (tid < M * M) sA[tid] = make_float2(A_re[tid], A_im[tid]);
    if (tid < M * NP) {
        int b = tid / NP, c = tid - b * NP;
        sB[b][c] = make_float2(B_re[b * M + c], B_im[b * M + c]);
    }
    if (tid < M) {
        float sn, cs;
        sincosf(x[ss * M + tid], &sn, &cs);
        ph[tid] = make_float2(cs, sn);
    }
    __syncthreads();

    if (tid < M * NP) {
        const int a = tid / NP;
        const int c = tid - a * NP;
        float2 acc = make_float2(0.f, 0.f);
#pragma unroll
        for (int b = 0; b < M; ++b) {
            float2 t  = cmul(ph[b], sB[b][c]);
            float2 Av = sA[a * M + b];
            acc.x += Av.x * t.x - Av.y * t.y;
            acc.y += Av.x * t.y + Av.y * t.x;
        }
        const int base = (ss * UC + tid) * 2;
        if (second) {
            g_u2d[base + 0] = make_float2(acc.x, acc.x);     // aR (conj re)
            g_u2d[base + 1] = make_float2(-acc.y, -acc.y);   // aI (conj im)
        } else {
            g_u1d[base + 0] = make_float2(acc.x, acc.y);     // bp
            g_u1d[base + 1] = make_float2(-acc.y, acc.x);    // bn
        }
    }
}

// ---------------------------------------------------------------------------
// Stage 2: W[a][b] = sum_k conjU2[j][k][a]*U1[i][k][b] (FFMA2, R6 GEMM),
// then Glynn permanent via DUAL 16-step Gray chains (delta5 = +/-1) with
// packed (re,im) rowsums. 16x16 pairs / 256 threads.
// ---------------------------------------------------------------------------
#define SP 145   // smem pitch in u64 (odd -> conflict-free)

__device__ __forceinline__ float2 prod6u(const u64* r) {
    float2 a0 = upk(r[0]), a1 = upk(r[1]), a2 = upk(r[2]);
    float2 a3 = upk(r[3]), a4 = upk(r[4]), a5 = upk(r[5]);
    float2 p01 = cmul(a0, a1);
    float2 p23 = cmul(a2, a3);
    float2 p45 = cmul(a4, a5);
    return cmul(cmul(p01, p23), p45);
}

__global__ __launch_bounds__(256, 2) void pair_kernel(float* __restrict__ out)
{
    __shared__ u64 s1[16 * SP];
    __shared__ u64 s2[16 * SP];

    const int i0  = blockIdx.y * 16;
    const int j0  = blockIdx.x * 16;
    const int tid = threadIdx.x;

    const u64* __restrict__ gu1 = (const u64*)g_u1d;
    const u64* __restrict__ gu2 = (const u64*)g_u2d;
    for (int e = tid; e < 16 * (UC * 2); e += 256) {
        int l = e / (UC * 2);
        int r = e - l * (UC * 2);
        s1[l * SP + r] = gu1[(i0 + l) * (UC * 2) + r];
        s2[l * SP + r] = gu2[(j0 + l) * (UC * 2) + r];
    }
    __syncthreads();

    const int lj = tid & 15;        // j fastest -> coalesced output
    const int li = tid >> 4;
    const u64* __restrict__ p1 = &s1[li * SP];   // bp/bn pairs
    const u64* __restrict__ p2 = &s2[lj * SP];   // aR/aI pairs

    u64 W[NP][NP];

    // k = 0 initializes W
    {
        u64 bb[12];
#pragma unroll
        for (int e = 0; e < 12; ++e) bb[e] = p1[e];
#pragma unroll
        for (int a = 0; a < NP; ++a) {
            const u64 aR = p2[2 * a + 0];
            const u64 aI = p2[2 * a + 1];
#pragma unroll
            for (int b = 0; b < NP; ++b)
                W[a][b] = ffma2(aI, bb[2 * b + 1], fmul2(aR, bb[2 * b]));
        }
    }

#pragma unroll
    for (int k = 1; k < M; ++k) {
        u64 bb[12];
#pragma unroll
        for (int e = 0; e < 12; ++e) bb[e] = p1[k * 12 + e];
#pragma unroll
        for (int a = 0; a < NP; ++a) {
            const u64 aR = p2[k * 12 + 2 * a + 0];
            const u64 aI = p2[k * 12 + 2 * a + 1];
#pragma unroll
            for (int b = 0; b < NP; ++b) {
                W[a][b] = ffma2(aR, bb[2 * b + 0], W[a][b]);
                W[a][b] = ffma2(aI, bb[2 * b + 1], W[a][b]);
            }
        }
    }

    // --- Glynn permanent, n=6, DUAL Gray chains (delta5 = +1 / -1) ---
    // Both chains walk rows 1..4 with the same gray schedule (16 steps).
    // After this init, W rows 0 and 5 are dead -> lower live registers.
    const u64 PL2 = pk2(2.f, 2.f);
    const u64 MI2 = pk2(-2.f, -2.f);

    u64 rA[NP], rB[NP];
#pragma unroll
    for (int j = 0; j < NP; ++j) {
        u64 t01 = fadd2(W[0][j], W[1][j]);
        u64 t23 = fadd2(W[2][j], W[3][j]);
        u64 t45 = fadd2(W[4][j], W[5][j]);
        rA[j] = fadd2(fadd2(t01, t23), t45);
        rB[j] = ffma2(MI2, W[5][j], rA[j]);   // delta5 = -1
    }

    float2 acc;
    {
        float2 pA = prod6u(rA);
        float2 pB = prod6u(rB);
        acc = make_float2(pA.x - pB.x, pA.y - pB.y);  // parity B = -parity A
    }

#pragma unroll
    for (int t = 1; t < 16; ++t) {
        const int bit = (t & 1) ? 0 : ((t & 2) ? 1 : ((t & 4) ? 2 : 3));
        const int a   = bit + 1;                              // flipped row (1..4)
        const bool neg = (((t ^ (t >> 1)) >> bit) & 1) != 0;
        const u64 c2  = neg ? MI2 : PL2;
        const float sg = (t & 1) ? -1.f : 1.f;                // chain-A parity

#pragma unroll
        for (int j = 0; j < NP; ++j) {
            rA[j] = ffma2(c2, W[a][j], rA[j]);
            rB[j] = ffma2(c2, W[a][j], rB[j]);
        }
        float2 pA = prod6u(rA);
        float2 pB = prod6u(rB);
        acc.x += sg * (pA.x - pB.x);
        acc.y += sg * (pA.y - pB.y);
    }

    // perm = acc / 32 ; K = |perm|^2 = |acc|^2 / 1024
    const float K = (acc.x * acc.x + acc.y * acc.y) * (1.0f / 1024.0f);
    out[(i0 + li) * N_SAMP + (j0 + lj)] = K;
}

// ---------------------------------------------------------------------------
extern "C" void kernel_launch(void* const* d_in, const int* in_sizes, int n_in,
                              void* d_out, int out_size)
{
    const float* x1   = (const float*)d_in[0];
    const float* x2   = (const float*)d_in[1];
    const float* A_re = (const float*)d_in[2];
    const float* A_im = (const float*)d_in[3];
    const float* B_re = (const float*)d_in[4];
    const float* B_im = (const float*)d_in[5];

    build_u_kernel<<<2 * N_SAMP, 160>>>(x1, x2, A_re, A_im, B_re, B_im);

    dim3 grid(N_SAMP / 16, N_SAMP / 16);   // 24 x 24
    pair_kernel<<<grid, 256>>>((float*)d_out);
}